// round 16
// baseline (speedup 1.0000x reference)
#include <cuda_runtime.h>
#include <cuda_bf16.h>
#include <float.h>
#include <limits.h>
#include <stdint.h>

// Problem shape (fixed by the dataset): Q=256, D=768, N=400000.
#define DDIM   768
#define MAXQ   256
#define MAXN   400000
#define CAND   32

// GEMM tiling
#define NT      128                  // N cols per CTA
#define KC      64                   // K per chunk
#define NUMK    (DDIM / KC)          // 12
#define THREADS 512
#define APITCH  80                   // bytes per A smem row (16B-aligned, ldmatrix conflict-free)
#define BPITCH  80
#define A_SZ    (256 * APITCH)       // 20480
#define B_SZ    (NT * BPITCH)        // 10240
#define STG     (A_SZ + B_SZ)        // 30720
#define DYN_SMEM (2 * STG)           // 61440

// Scratch (allocations are banned -> __device__ globals)
__device__ __align__(16) float         g_qn  [MAXQ * DDIM];                  // L1-normalized queries (fp32)
__device__ __align__(16) int8_t        g_qi8 [MAXQ * DDIM];                  // per-row-scaled int8 queries
__device__ __align__(16) __nv_bfloat16 g_sims[(size_t)MAXQ * (size_t)MAXN]; // bf16 raw int scores (~205MB)
__device__ unsigned int g_emax_bits;
__device__ float        g_escale;

// ---------------------------------------------------------------------------
// emb scale estimation: reset -> sampled max -> finalize
// ---------------------------------------------------------------------------
__global__ void einit_kernel() { g_emax_bits = 0u; }

__global__ void esample_kernel(const float* __restrict__ emb, int N, int D) {
    int r   = (blockIdx.x >> 2) * 8;        // rows 0,8,...  (96 rows sampled)
    int seg = blockIdx.x & 3;
    if (r >= D) return;
    const float* row = emb + (size_t)r * N;
    int lo = (int)(((long long)N * seg) / 4);
    int hi = (int)(((long long)N * (seg + 1)) / 4);
    float m = 0.f;
    for (int i = lo + threadIdx.x; i < hi; i += blockDim.x)
        m = fmaxf(m, fabsf(row[i]));
    #pragma unroll
    for (int o = 16; o > 0; o >>= 1)
        m = fmaxf(m, __shfl_xor_sync(0xffffffffu, m, o));
    __shared__ float wm[8];
    if ((threadIdx.x & 31) == 0) wm[threadIdx.x >> 5] = m;
    __syncthreads();
    if (threadIdx.x == 0) {
        float t = 0.f;
        int nw = (blockDim.x + 31) >> 5;
        for (int i = 0; i < nw; i++) t = fmaxf(t, wm[i]);
        atomicMax(&g_emax_bits, __float_as_uint(t));
    }
}

__global__ void efinal_kernel() {
    float m = __uint_as_float(g_emax_bits);
    g_escale = 127.0f / (1.25f * fmaxf(m, 1e-20f));
}

// ---------------------------------------------------------------------------
// Kernel 1: L1-normalize queries -> fp32 (rescore) + per-row-scaled int8 (GEMM)
// ---------------------------------------------------------------------------
__global__ void normq_kernel(const float* __restrict__ q, int Q) {
    int row = blockIdx.x;
    int tid = threadIdx.x;

    if (row >= Q) {   // pad rows so the M=256 tile is harmless
        for (int d = tid; d < DDIM; d += 256) {
            g_qn [(size_t)row * DDIM + d] = 0.f;
            g_qi8[(size_t)row * DDIM + d] = 0;
        }
        return;
    }

    float s = 0.f, mx = 0.f;
    for (int d = tid; d < DDIM; d += 256) {
        float v = q[(size_t)row * DDIM + d];
        s  += fabsf(v);
        mx  = fmaxf(mx, fabsf(v));
    }
    #pragma unroll
    for (int o = 16; o > 0; o >>= 1) {
        s  += __shfl_xor_sync(0xffffffffu, s, o);
        mx  = fmaxf(mx, __shfl_xor_sync(0xffffffffu, mx, o));
    }
    __shared__ float ws[8], wmx[8];
    __shared__ float inv, qs;
    if ((tid & 31) == 0) { ws[tid >> 5] = s; wmx[tid >> 5] = mx; }
    __syncthreads();
    if (tid == 0) {
        float t = 0.f, m = 0.f;
        #pragma unroll
        for (int i = 0; i < 8; i++) { t += ws[i]; m = fmaxf(m, wmx[i]); }
        inv = 1.f / fmaxf(t, 1e-12f);
        qs  = (m > 0.f) ? (127.0f / m) : 0.f;   // int8 = raw * 127/maxraw (per-row scale
                                                 // never changes that row's ranking)
    }
    __syncthreads();

    float iv = inv, sc = qs;
    for (int d = tid; d < DDIM; d += 256) {
        float raw = q[(size_t)row * DDIM + d];
        g_qn[(size_t)row * DDIM + d] = raw * iv;
        int r;
        asm("cvt.rni.sat.s8.f32 %0, %1;" : "=r"(r) : "f"(raw * sc));
        g_qi8[(size_t)row * DDIM + d] = (int8_t)r;
    }
}

// ---------------------------------------------------------------------------
// int8 quantize+pack helpers
// ---------------------------------------------------------------------------
__device__ __forceinline__ uint32_t qpack4(float4 v, float S) {
    uint32_t r0, r1, r2, r3;
    asm("cvt.rni.sat.s8.f32 %0, %1;" : "=r"(r0) : "f"(v.x * S));
    asm("cvt.rni.sat.s8.f32 %0, %1;" : "=r"(r1) : "f"(v.y * S));
    asm("cvt.rni.sat.s8.f32 %0, %1;" : "=r"(r2) : "f"(v.z * S));
    asm("cvt.rni.sat.s8.f32 %0, %1;" : "=r"(r3) : "f"(v.w * S));
    return __byte_perm(__byte_perm(r0, r1, 0x0040),
                       __byte_perm(r2, r3, 0x0040), 0x5410);
}

// ---------------------------------------------------------------------------
// Kernel 2: int8 IMMA GEMM  sims[256,N] = qi8[256,768] @ int8(emb[768,N])
// CTA tile 256x128, K-chunk 64, 512 threads (16 warps 4Mx4N, warp tile 64x32),
// double-buffered smem, 1 barrier/chunk. Output = bf16(raw int score) —
// bf16 (not fp16!) because raw scores reach ~8e4 > fp16 max 65504.
// ---------------------------------------------------------------------------
__global__ void __launch_bounds__(THREADS)
gemm_i8_kernel(const float* __restrict__ Bm, int N) {
    extern __shared__ __align__(16) char smem[];

    const int tid  = threadIdx.x;
    const int lane = tid & 31;
    const int wid  = tid >> 5;      // 0..15
    const int wm   = wid & 3;       // M block (64 rows)
    const int wn   = wid >> 2;      // N block (32 cols)
    const int nBase = blockIdx.x * NT;
    const float S  = g_escale;

    int acc[4][4][4];
    #pragma unroll
    for (int i = 0; i < 4; i++)
        #pragma unroll
        for (int j = 0; j < 4; j++)
            #pragma unroll
            for (int r = 0; r < 4; r++) acc[i][j][r] = 0;

    // --- staging assignments ---
    const int mA = tid >> 1;              // A: row 0..255
    const int hA = (tid & 1) * 32;        // A: k-half offset (bytes)
    const int bK0 = wid * 4;              // B: 4 k-rows per warp
    const int bN0 = lane * 4;             // B: 4 n-cols per lane

    uint4  stA0, stA1;
    float4 stB[4];

    auto loadA = [&](int c) {
        const int8_t* src = g_qi8 + (size_t)mA * DDIM + c * KC + hA;
        stA0 = *(const uint4*)(src);
        stA1 = *(const uint4*)(src + 16);
    };
    auto loadB = [&](int c) {
        int kB = c * KC + bK0;
        int n  = nBase + bN0;
        if (n + 3 < N && ((N & 3) == 0)) {
            #pragma unroll
            for (int j = 0; j < 4; j++)
                stB[j] = *(const float4*)(Bm + (size_t)(kB + j) * N + n);
        } else {
            #pragma unroll
            for (int j = 0; j < 4; j++) {
                float t[4];
                #pragma unroll
                for (int e = 0; e < 4; e++)
                    t[e] = (n + e < N) ? Bm[(size_t)(kB + j) * N + n + e] : 0.f;
                stB[j] = make_float4(t[0], t[1], t[2], t[3]);
            }
        }
    };
    auto storeTiles = [&](int stage) {
        char* As = smem + stage * STG;
        char* Bs = As + A_SZ;
        // A: two 16B stores
        char* da = As + mA * APITCH + hA;
        *(uint4*)da        = stA0;
        *(uint4*)(da + 16) = stA1;
        // B: quantize rows (4 n at one k), byte-transpose 4x4 -> (4 k at one n)
        uint32_t r0 = qpack4(stB[0], S);
        uint32_t r1 = qpack4(stB[1], S);
        uint32_t r2 = qpack4(stB[2], S);
        uint32_t r3 = qpack4(stB[3], S);
        uint32_t c0 = __byte_perm(__byte_perm(r0, r1, 0x0040), __byte_perm(r2, r3, 0x0040), 0x5410);
        uint32_t c1 = __byte_perm(__byte_perm(r0, r1, 0x0051), __byte_perm(r2, r3, 0x0051), 0x5410);
        uint32_t c2 = __byte_perm(__byte_perm(r0, r1, 0x0062), __byte_perm(r2, r3, 0x0062), 0x5410);
        uint32_t c3 = __byte_perm(__byte_perm(r0, r1, 0x0073), __byte_perm(r2, r3, 0x0073), 0x5410);
        char* db = Bs + bN0 * BPITCH + bK0;
        *(uint32_t*)(db)              = c0;
        *(uint32_t*)(db + BPITCH)     = c1;
        *(uint32_t*)(db + 2 * BPITCH) = c2;
        *(uint32_t*)(db + 3 * BPITCH) = c3;
    };
    auto compute = [&](int stage) {
        char* As = smem + stage * STG;
        char* Bs = As + A_SZ;
        #pragma unroll
        for (int ks = 0; ks < 2; ++ks) {
            uint32_t b[4][2];
            #pragma unroll
            for (int ni = 0; ni < 4; ++ni) {
                const char* p = Bs + (wn * 32 + ni * 8 + (lane & 7)) * BPITCH
                                   + ks * 32 + ((lane >> 3) & 1) * 16;
                uint32_t addr = (uint32_t)__cvta_generic_to_shared(p);
                asm volatile("ldmatrix.sync.aligned.m8n8.x2.shared.b16 {%0,%1}, [%2];"
                             : "=r"(b[ni][0]), "=r"(b[ni][1]) : "r"(addr));
            }
            #pragma unroll
            for (int mi = 0; mi < 4; ++mi) {
                uint32_t a[4];
                const char* p = As + (wm * 64 + mi * 16 + (lane & 15)) * APITCH
                                   + ks * 32 + (lane >> 4) * 16;
                uint32_t addr = (uint32_t)__cvta_generic_to_shared(p);
                asm volatile("ldmatrix.sync.aligned.m8n8.x4.shared.b16 {%0,%1,%2,%3}, [%4];"
                             : "=r"(a[0]), "=r"(a[1]), "=r"(a[2]), "=r"(a[3]) : "r"(addr));
                #pragma unroll
                for (int ni = 0; ni < 4; ++ni)
                    asm volatile(
                        "mma.sync.aligned.m16n8k32.row.col.s32.s8.s8.s32 "
                        "{%0,%1,%2,%3}, {%4,%5,%6,%7}, {%8,%9}, {%0,%1,%2,%3};"
                        : "+r"(acc[mi][ni][0]), "+r"(acc[mi][ni][1]),
                          "+r"(acc[mi][ni][2]), "+r"(acc[mi][ni][3])
                        : "r"(a[0]), "r"(a[1]), "r"(a[2]), "r"(a[3]),
                          "r"(b[ni][0]), "r"(b[ni][1]));
            }
        }
    };

    // ---- pipeline: double buffer, one barrier per chunk ----
    loadA(0); loadB(0);
    storeTiles(0);
    __syncthreads();

    for (int c = 0; c < NUMK; ++c) {
        if (c + 1 < NUMK) { loadA(c + 1); loadB(c + 1); }
        compute(c & 1);
        if (c + 1 < NUMK) {
            storeTiles((c + 1) & 1);
            __syncthreads();
        }
    }

    // ---- epilogue: s32 -> bf16 raw scores ----
    const int rBase = wm * 64 + (lane >> 2);
    const int cBase = wn * 32 + (lane & 3) * 2;
    const bool even = ((N & 1) == 0);
    #pragma unroll
    for (int mi = 0; mi < 4; ++mi) {
        int r0 = rBase + mi * 16;
        int r1 = r0 + 8;
        #pragma unroll
        for (int ni = 0; ni < 4; ++ni) {
            int gcol = nBase + cBase + ni * 8;
            if (gcol + 1 < N && even) {
                __nv_bfloat162 v01 = __floats2bfloat162_rn((float)acc[mi][ni][0], (float)acc[mi][ni][1]);
                __nv_bfloat162 v23 = __floats2bfloat162_rn((float)acc[mi][ni][2], (float)acc[mi][ni][3]);
                *(__nv_bfloat162*)(g_sims + (size_t)r0 * N + gcol) = v01;
                *(__nv_bfloat162*)(g_sims + (size_t)r1 * N + gcol) = v23;
            } else {
                if (gcol < N) {
                    g_sims[(size_t)r0 * N + gcol] = __float2bfloat16_rn((float)acc[mi][ni][0]);
                    g_sims[(size_t)r1 * N + gcol] = __float2bfloat16_rn((float)acc[mi][ni][2]);
                }
                if (gcol + 1 < N) {
                    g_sims[(size_t)r0 * N + gcol + 1] = __float2bfloat16_rn((float)acc[mi][ni][1]);
                    g_sims[(size_t)r1 * N + gcol + 1] = __float2bfloat16_rn((float)acc[mi][ni][3]);
                }
            }
        }
    }
}

// ---------------------------------------------------------------------------
// Kernel 3: masked top-32 candidates from bf16 scores, exact fp32 rescore, top-4
// Tie-break matches jax.lax.top_k: equal value -> lower index wins.
// ---------------------------------------------------------------------------
__global__ void topk_rescore_kernel(const float* __restrict__ emb,
                                    const int* __restrict__ startp,
                                    const int* __restrict__ endp,
                                    float* __restrict__ out, int N, int Q) {
    int q = blockIdx.x;
    if (q >= Q) return;
    int tid = threadIdx.x;
    int start = startp[0];
    int end   = endp[0];

    const __nv_bfloat16* __restrict__ row = g_sims + (size_t)q * N;

    // per-thread top-4 (strict > keeps lowest index)
    float bv[4] = {-FLT_MAX, -FLT_MAX, -FLT_MAX, -FLT_MAX};
    int   bi[4] = {INT_MAX, INT_MAX, INT_MAX, INT_MAX};
    for (int n = tid; n < N; n += 256) {
        if (n >= start && n < end) continue;
        float v = __bfloat162float(row[n]);
        if (v > bv[3]) {
            bv[3] = v; bi[3] = n;
            #pragma unroll
            for (int p = 3; p > 0; p--) {
                if (bv[p] > bv[p-1]) {
                    float tv = bv[p-1]; bv[p-1] = bv[p]; bv[p] = tv;
                    int   ti = bi[p-1]; bi[p-1] = bi[p]; bi[p] = ti;
                }
            }
        }
    }

    __shared__ float sv[256 * 4];
    __shared__ int   si[256 * 4];
    #pragma unroll
    for (int j = 0; j < 4; j++) { sv[tid * 4 + j] = bv[j]; si[tid * 4 + j] = bi[j]; }
    __syncthreads();

    __shared__ int   candIdx[CAND];
    __shared__ float candVal[CAND];
    if (tid == 0) {
        float rv[CAND]; int ri[CAND];
        #pragma unroll
        for (int i = 0; i < CAND; i++) { rv[i] = -FLT_MAX; ri[i] = INT_MAX; }
        for (int t = 0; t < 256 * 4; t++) {
            float v = sv[t]; int idx = si[t];
            if (idx == INT_MAX) continue;
            if (v > rv[CAND-1] || (v == rv[CAND-1] && idx < ri[CAND-1])) {
                rv[CAND-1] = v; ri[CAND-1] = idx;
                #pragma unroll
                for (int p = CAND-1; p > 0; p--) {
                    if (rv[p] > rv[p-1] || (rv[p] == rv[p-1] && ri[p] < ri[p-1])) {
                        float tv = rv[p-1]; rv[p-1] = rv[p]; rv[p] = tv;
                        int   ti = ri[p-1]; ri[p-1] = ri[p]; ri[p] = ti;
                    }
                }
            }
        }
        #pragma unroll
        for (int i = 0; i < CAND; i++) candIdx[i] = ri[i];
    }
    __syncthreads();

    // exact fp32 rescore: 32 candidates x 8 lanes each
    int c = tid >> 3;
    int l = tid & 7;
    int idx = candIdx[c];
    float s = 0.f;
    if (idx >= 0 && idx < N) {
        const float* __restrict__ qrow = g_qn + (size_t)q * DDIM;
        for (int d = l; d < DDIM; d += 8)
            s += qrow[d] * emb[(size_t)d * N + idx];
    }
    #pragma unroll
    for (int o = 4; o > 0; o >>= 1)
        s += __shfl_down_sync(0xffffffffu, s, o, 8);
    if (l == 0) candVal[c] = (idx >= 0 && idx < N) ? s : -FLT_MAX;
    __syncthreads();

    if (tid == 0) {
        float fv[4] = {-FLT_MAX, -FLT_MAX, -FLT_MAX, -FLT_MAX};
        int   fi[4] = {INT_MAX, INT_MAX, INT_MAX, INT_MAX};
        for (int cc = 0; cc < CAND; cc++) {
            float v = candVal[cc]; int ix = candIdx[cc];
            if (ix == INT_MAX) continue;
            if (v > fv[3] || (v == fv[3] && ix < fi[3])) {
                fv[3] = v; fi[3] = ix;
                #pragma unroll
                for (int p = 3; p > 0; p--) {
                    if (fv[p] > fv[p-1] || (fv[p] == fv[p-1] && fi[p] < fi[p-1])) {
                        float tv = fv[p-1]; fv[p-1] = fv[p]; fv[p] = tv;
                        int   ti = fi[p-1]; fi[p-1] = fi[p]; fi[p] = ti;
                    }
                }
            }
        }
        #pragma unroll
        for (int j = 0; j < 4; j++) {
            out[(size_t)q * 4 + j]                 = fv[j];         // values
            out[(size_t)Q * 4 + (size_t)q * 4 + j] = (float)fi[j];  // indices
        }
    }
}

// ---------------------------------------------------------------------------
extern "C" void kernel_launch(void* const* d_in, const int* in_sizes, int n_in,
                              void* d_out, int out_size) {
    const float* query = (const float*)d_in[0];   // [Q, 768]
    const float* emb   = (const float*)d_in[1];   // [768, N]
    const int* startp  = (const int*)d_in[2];
    const int* endp    = (const int*)d_in[3];
    float* out = (float*)d_out;

    int Q = in_sizes[0] / DDIM;
    int N = in_sizes[1] / DDIM;
    if (Q <= 0 || N <= 0) return;
    if (Q > MAXQ || N > MAXN) return;

    cudaFuncSetAttribute(gemm_i8_kernel,
                         cudaFuncAttributeMaxDynamicSharedMemorySize, DYN_SMEM);

    einit_kernel<<<1, 1>>>();
    esample_kernel<<<384, 256>>>(emb, N, DDIM);
    efinal_kernel<<<1, 1>>>();

    normq_kernel<<<MAXQ, 256>>>(query, Q);

    int gridN = (N + NT - 1) / NT;
    gemm_i8_kernel<<<gridN, THREADS, DYN_SMEM>>>(emb, N);

    topk_rescore_kernel<<<Q, 256>>>(emb, startp, endp, out, N, Q);
}